// round 6
// baseline (speedup 1.0000x reference)
#include <cuda_runtime.h>

#define B_SZ   512
#define F_SZ   512
#define NK     50
#define DK     16
#define NCOL   (NK*DK)     // 800
#define OUTW   (F_SZ + NK) // 562
#define KSPLIT 8
#define KCHUNK (F_SZ / KSPLIT)   // 64
#define ACT_SZ (B_SZ * NCOL)

__device__ float g_act_part[KSPLIT * ACT_SZ];  // split-K partials (m-major)
__device__ float g_act_T[NCOL * B_SZ];         // reduced, TRANSPOSED: [n][m]

// 10 tile-pairs (I<=J) over 4 row-tiles of 128
__constant__ int PAIR_I[10] = {0,0,0,0,1,1,1,2,2,3};
__constant__ int PAIR_J[10] = {0,1,2,3,1,2,3,2,3,3};

// ---------------------------------------------------------------------------
// GEMM split-K (unchanged): act_part[kc][m][n] += x[m][:]*W[:,n] over chunk
// ---------------------------------------------------------------------------
__global__ __launch_bounds__(256) void gemm_kernel(const float* __restrict__ A,
                                                   const float* __restrict__ Bm) {
    __shared__ float As[16][64];
    __shared__ float Bs[16][64];

    const int tid = threadIdx.x;
    const int m0  = blockIdx.y * 64;
    const int n0  = blockIdx.x * 64;
    const int kc  = blockIdx.z;
    float* out = g_act_part + kc * ACT_SZ;

    const int ty = tid >> 4;
    const int tx = tid & 15;

    float acc[4][4] = {};

    const int kbeg = kc * KCHUNK;
    for (int k0 = kbeg; k0 < kbeg + KCHUNK; k0 += 16) {
        #pragma unroll
        for (int p = 0; p < 4; p++) {
            int e = tid + p * 256;
            int r = e >> 4, c = e & 15;
            As[c][r] = A[(m0 + r) * F_SZ + (k0 + c)];
        }
        #pragma unroll
        for (int p = 0; p < 4; p++) {
            int e = tid + p * 256;
            int r = e >> 6, c = e & 63;
            int n = n0 + c;
            Bs[r][c] = (n < NCOL) ? Bm[(k0 + r) * NCOL + n] : 0.0f;
        }
        __syncthreads();

        #pragma unroll
        for (int kk = 0; kk < 16; kk++) {
            float a[4], b[4];
            #pragma unroll
            for (int i = 0; i < 4; i++) a[i] = As[kk][ty * 4 + i];
            #pragma unroll
            for (int j = 0; j < 4; j++) b[j] = Bs[kk][tx * 4 + j];
            #pragma unroll
            for (int i = 0; i < 4; i++)
                #pragma unroll
                for (int j = 0; j < 4; j++)
                    acc[i][j] += a[i] * b[j];
        }
        __syncthreads();
    }

    #pragma unroll
    for (int i = 0; i < 4; i++) {
        int m = m0 + ty * 4 + i;
        #pragma unroll
        for (int j = 0; j < 4; j++) {
            int n = n0 + tx * 4 + j;
            if (n < NCOL) out[m * NCOL + n] = acc[i][j];
        }
    }
}

// ---------------------------------------------------------------------------
// Reduce 8 split-K partials AND transpose: g_act_T[n][m] = sum_p part[p][m][n]
// 32x32 tiles, smem transpose, coalesced both sides. grid (16, 25).
// ---------------------------------------------------------------------------
__global__ __launch_bounds__(256) void reduce_T_kernel() {
    __shared__ float t[32][33];
    const int tm0 = blockIdx.x * 32;   // m tile
    const int tn0 = blockIdx.y * 32;   // n tile
    const int c = threadIdx.x & 31;
    const int r = threadIdx.x >> 5;    // 0..7

    #pragma unroll
    for (int q = 0; q < 4; q++) {
        int mi = r * 4 + q;
        int idx = (tm0 + mi) * NCOL + tn0 + c;   // coalesced over c
        float s = 0.0f;
        #pragma unroll
        for (int p = 0; p < KSPLIT; p++) s += g_act_part[p * ACT_SZ + idx];
        t[mi][c] = s;
    }
    __syncthreads();
    #pragma unroll
    for (int q = 0; q < 4; q++) {
        int ni = r * 4 + q;
        g_act_T[(tn0 + ni) * B_SZ + tm0 + c] = t[c][ni];   // coalesced over c
    }
}

// ---------------------------------------------------------------------------
// Copy x into out[:,0:512] and ZERO out[:,512:562]
// ---------------------------------------------------------------------------
__global__ __launch_bounds__(256) void prep_out_kernel(const float* __restrict__ x,
                                                       float* __restrict__ out) {
    int idx = blockIdx.x * 256 + threadIdx.x;   // 512*281 = 143872 exactly
    int b = idx / 281, j = idx - b * 281;
    float2 v;
    if (j < 256) v = ((const float2*)(x + (size_t)b * F_SZ))[j];
    else         v = make_float2(0.0f, 0.0f);
    ((float2*)(out + (size_t)b * OUTW))[j] = v;
}

// ---------------------------------------------------------------------------
// Symmetric pairwise, 32-col chunks, ring-rotated column sums.
// grid = (40, 50): blockIdx.x = pair*4 + chunk. block = 128 threads.
// Thread t owns row I*128+t (16 coalesced LDG.32 from g_act_T).
// 32-col J-chunk staged in padded smem (row stride 20 floats -> rotated
// LDS.128 reads conflict-free). Off-diag: column sums via 1-shfl ring.
// ---------------------------------------------------------------------------
__global__ __launch_bounds__(128) void pairwise_kernel(float* __restrict__ out) {
    __shared__ float sJ[32][20];        // 2.5 KB, padded
    __shared__ float colpart[4][32];

    const int bx   = blockIdx.x;
    const int pair = bx >> 2;
    const int c0   = (bx & 3) * 32;
    const int I = PAIR_I[pair];
    const int J = PAIR_J[pair];
    const int k   = blockIdx.y;
    const int tid = threadIdx.x;
    const int lane = tid & 31;
    const int w    = tid >> 5;

    // stage J chunk: 32 cols x 16 d = 512 floats; float4-coalesced reads
    {
        int d  = tid >> 3;          // 0..15
        int m4 = (tid & 7) * 4;     // 0,4,...,28
        float4 v = *(const float4*)(g_act_T + (k * DK + d) * B_SZ + J * 128 + c0 + m4);
        sJ[m4 + 0][d] = v.x;
        sJ[m4 + 1][d] = v.y;
        sJ[m4 + 2][d] = v.z;
        sJ[m4 + 3][d] = v.w;
    }

    // own row: 16 coalesced scalar loads
    float a[16];
    const int rowB = I * 128 + tid;
    #pragma unroll
    for (int d = 0; d < 16; d++)
        a[d] = g_act_T[(k * DK + d) * B_SZ + rowB];
    __syncthreads();

    const bool diag = (I == J);
    float rowAcc = 0.0f;
    float racc   = 0.0f;   // rotating column partial (off-diag only)

    #pragma unroll 4
    for (int s = 0; s < 32; s++) {
        int j = (lane + s) & 31;
        const float4* vp = (const float4*)sJ[j];
        float4 v0 = vp[0], v1 = vp[1], v2 = vp[2], v3 = vp[3];
        float p0 = fabsf(a[0]  - v0.x) + fabsf(a[1]  - v0.y)
                 + fabsf(a[2]  - v0.z) + fabsf(a[3]  - v0.w);
        float p1 = fabsf(a[4]  - v1.x) + fabsf(a[5]  - v1.y)
                 + fabsf(a[6]  - v1.z) + fabsf(a[7]  - v1.w);
        float p2 = fabsf(a[8]  - v2.x) + fabsf(a[9]  - v2.y)
                 + fabsf(a[10] - v2.z) + fabsf(a[11] - v2.w);
        float p3 = fabsf(a[12] - v3.x) + fabsf(a[13] - v3.y)
                 + fabsf(a[14] - v3.z) + fabsf(a[15] - v3.w);
        float e = __expf(-((p0 + p1) + (p2 + p3)));
        rowAcc += e;
        if (!diag) {
            // ring: lane L holds partial for column (L+s)&31 == j; add, rotate
            racc += e;
            racc = __shfl_sync(0xFFFFFFFFu, racc, (lane + 1) & 31);
        }
    }

    float* fbase = out + F_SZ + k;
    atomicAdd(fbase + (size_t)rowB * OUTW, rowAcc);

    if (!diag) {
        // after 32 rotations, lane L holds colSum for local column L (this warp's rows)
        colpart[w][lane] = racc;
        __syncthreads();
        if (tid < 32) {
            float cs = colpart[0][tid] + colpart[1][tid]
                     + colpart[2][tid] + colpart[3][tid];
            atomicAdd(fbase + (size_t)(J * 128 + c0 + tid) * OUTW, cs);
        }
    }
}

// ---------------------------------------------------------------------------
extern "C" void kernel_launch(void* const* d_in, const int* in_sizes, int n_in,
                              void* d_out, int out_size) {
    const float* x = (const float*)d_in[0];
    const float* W = (const float*)d_in[1];
    float* out = (float*)d_out;

    dim3 gemm_grid((NCOL + 63) / 64, B_SZ / 64, KSPLIT);   // 13 x 8 x 8
    gemm_kernel<<<gemm_grid, 256>>>(x, W);

    dim3 red_grid(B_SZ / 32, NCOL / 32);                   // 16 x 25
    reduce_T_kernel<<<red_grid, 256>>>();

    prep_out_kernel<<<562, 256>>>(x, out);                 // copy + zero

    dim3 pw_grid(40, NK);                                  // 40 x 50 = 2000
    pairwise_kernel<<<pw_grid, 128>>>(out);
}